// round 16
// baseline (speedup 1.0000x reference)
#include <cuda_runtime.h>
#include <cuda_bf16.h>
#include <mma.h>
#include <cstdint>

using namespace nvcuda;

#define BB    2
#define CC    64
#define NPOS  131072
#define HEADS 4
#define DHEAD 32
#define HID   128
#define TPB   256
#define POSB  128
#define LDX   72      // bf16 tile ld: 144B rows -> conflict-free LDSM
#define LDQ   40      // q tile ld: 80B rows -> conflict-free
#define LDE   136     // ek/vv bf16 tile ld: 272B rows -> conflict-free

typedef unsigned long long u64;
typedef unsigned int       u32;

// ---------------- device scratch ----------------
__device__ float g_ctx[BB * HEADS * DHEAD * DHEAD];
__device__ float g_Z[BB * HEADS * DHEAD];
__device__ __nv_bfloat16 g_Wh[384 * LDX];      // wqkv split hi, padded rows [row][LDX]
__device__ __nv_bfloat16 g_Wl[384 * LDX];      // wqkv split lo
__device__ __nv_bfloat16 g_Mh[BB][HID * LDX];  // M split hi, padded rows [i][LDX]
__device__ __nv_bfloat16 g_Ml[BB][HID * LDX];  // M split lo

__device__ __forceinline__ void bsplit(float v, __nv_bfloat16& h, __nv_bfloat16& l) {
    h = __float2bfloat16_rn(v);
    l = __float2bfloat16_rn(v - __bfloat162float(h));
}

// ---------------- kernel 0: zero accumulators + pre-split W ----------------
__global__ void la_zero_kernel(const float* __restrict__ wqkv) {
    int i = blockIdx.x * blockDim.x + threadIdx.x;
    if (i < BB * HEADS * DHEAD * DHEAD) g_ctx[i] = 0.f;
    if (i < BB * HEADS * DHEAD)         g_Z[i]   = 0.f;
    for (int j = i; j < 384 * 64; j += 33 * 256) {
        int row = j >> 6, k = j & 63;
        __nv_bfloat16 h, l; bsplit(__ldg(wqkv + (size_t)row * 64 + k), h, l);
        g_Wh[row * LDX + k] = h;
        g_Wl[row * LDX + k] = l;
    }
}

// full-thread LN into split-bf16 A tiles (2 threads per position), scratch = 512 floats
__device__ __forceinline__ void ln_to_tiles(const float* __restrict__ x, int bb, int pos0, int t,
                                            __nv_bfloat16* xh, __nv_bfloat16* xl,
                                            float* scratch, const float* g1s, const float* b1s) {
    const int p = t & 127, half = t >> 7;
    const float* xb = x + (size_t)bb * CC * NPOS + pos0 + p;
    float xr[32];
    float s = 0.f, s2 = 0.f;
#pragma unroll
    for (int c = 0; c < 32; c++) {
        float v = __ldg(xb + (size_t)(half * 32 + c) * NPOS);
        xr[c] = v; s += v; s2 += v * v;
    }
    scratch[half * 128 + p]       = s;
    scratch[256 + half * 128 + p] = s2;
    __syncthreads();
    float st  = scratch[p] + scratch[128 + p];
    float st2 = scratch[256 + p] + scratch[384 + p];
    float mean = st * (1.f / 64.f);
    float rstd = rsqrtf(st2 * (1.f / 64.f) - mean * mean + 1e-5f);
#pragma unroll
    for (int i = 0; i < 16; i++) {
        int ch = half * 32 + 2 * i;
        float v0 = (xr[2 * i]     - mean) * rstd * g1s[ch]     + b1s[ch];
        float v1 = (xr[2 * i + 1] - mean) * rstd * g1s[ch + 1] + b1s[ch + 1];
        __nv_bfloat16 h0, l0, h1, l1;
        bsplit(v0, h0, l0); bsplit(v1, h1, l1);
        *(u32*)(xh + p * LDX + ch) = (u32)__bfloat16_as_ushort(h0) | ((u32)__bfloat16_as_ushort(h1) << 16);
        *(u32*)(xl + p * LDX + ch) = (u32)__bfloat16_as_ushort(l0) | ((u32)__bfloat16_as_ushort(l1) << 16);
    }
}

// ================= pass1: LN + wmma K/V GEMM + wmma ctx GEMM + Z =================
#define P1_XH  0                     // 128*72*2 = 18432
#define P1_XL  18432
#define P1_WH  36864                 // 64*72*2 = 9216 (K rows 0-31, V rows 32-63)
#define P1_WL  46080
#define P1_EKF 55296                 // fp32 32x132 = 16896 (also LN scratch)
#define P1_VVF 72192                 // fp32 32x132
// bf16 overlay of the fp32 region (written after regs are loaded + sync):
#define P1_EKH 55296                 // 32*136*2 = 8704
#define P1_EKL 64000
#define P1_VVH 72704
#define P1_VVL 81408                 // ends 90112
#define P1_CB  90112                 // 8 warp ctx bufs 16x20 fp32 = 10240
#define P1_G1  100352
#define P1_B1  100608
#define P1_BYTES 100864

__global__ __launch_bounds__(TPB, 2)
void la_pass1_kernel(const float* __restrict__ x, const float* __restrict__ g1,
                     const float* __restrict__ b1) {
    extern __shared__ char smem[];
    __nv_bfloat16* xh  = (__nv_bfloat16*)(smem + P1_XH);
    __nv_bfloat16* xl  = (__nv_bfloat16*)(smem + P1_XL);
    __nv_bfloat16* wh  = (__nv_bfloat16*)(smem + P1_WH);
    __nv_bfloat16* wl  = (__nv_bfloat16*)(smem + P1_WL);
    float* ekf = (float*)(smem + P1_EKF);
    float* vvf = (float*)(smem + P1_VVF);
    __nv_bfloat16* ekh = (__nv_bfloat16*)(smem + P1_EKH);
    __nv_bfloat16* ekl = (__nv_bfloat16*)(smem + P1_EKL);
    __nv_bfloat16* vvh = (__nv_bfloat16*)(smem + P1_VVH);
    __nv_bfloat16* vvl = (__nv_bfloat16*)(smem + P1_VVL);
    float* cb  = (float*)(smem + P1_CB);
    float* g1s = (float*)(smem + P1_G1);
    float* b1s = (float*)(smem + P1_B1);

    const int t   = threadIdx.x;
    const int wid = t >> 5;
    const int bb   = blockIdx.y;
    const int pos0 = blockIdx.x * POSB;

    if (t < 64) { g1s[t] = g1[t]; b1s[t] = b1[t]; }
    ln_to_tiles(x, bb, pos0, t, xh, xl, ekf, g1s, b1s);
    __syncthreads();

    // hoist x A fragments (invariant across heads)
    wmma::fragment<wmma::matrix_a, 16, 16, 16, __nv_bfloat16, wmma::row_major> fAh[4], fAl[4];
#pragma unroll
    for (int kt = 0; kt < 4; kt++) {
        wmma::load_matrix_sync(fAh[kt], xh + wid * 16 * LDX + kt * 16, LDX);
        wmma::load_matrix_sync(fAl[kt], xl + wid * 16 * LDX + kt * 16, LDX);
    }

    // split-pass ownership: row d = t>>3, positions pl..pl+15
    const int sd = t >> 3, pl = (t & 7) * 16;
    // ctx GEMM ownership: warp -> (kh, mt, nt)
    const int kh = wid >> 2, mt = (wid >> 1) & 1, ctn = wid & 1;

    for (int h = 0; h < HEADS; h++) {
        // ---- stage K_h/V_h: pure uint4 copies of pre-split, pre-padded rows ----
        {
            uint4* dh = (uint4*)wh;
            uint4* dl = (uint4*)wl;
            const uint4* sh = (const uint4*)g_Wh;
            const uint4* sl = (const uint4*)g_Wl;
            for (int idx = t; idx < 576; idx += TPB) {
                int r = idx / 9, q = idx - r * 9;            // local row 0..63
                int srow = (r < 32) ? (128 + h * 32 + r) : (224 + h * 32 + r);
                dh[idx] = sh[srow * 9 + q];
                dl[idx] = sl[srow * 9 + q];
            }
        }
        __syncthreads();

        // ---- K/V GEMM; exp applied elementwise in the K fragments ----
        {
            wmma::fragment<wmma::accumulator, 16, 16, 16, float> accK[2], accV[2];
#pragma unroll
            for (int nt = 0; nt < 2; nt++) { wmma::fill_fragment(accK[nt], 0.f); wmma::fill_fragment(accV[nt], 0.f); }
#pragma unroll
            for (int kt = 0; kt < 4; kt++) {
#pragma unroll
                for (int nt = 0; nt < 2; nt++) {
                    wmma::fragment<wmma::matrix_b, 16, 16, 16, __nv_bfloat16, wmma::col_major> fBh, fBl;
                    wmma::load_matrix_sync(fBh, wh + (nt * 16) * LDX + kt * 16, LDX);
                    wmma::load_matrix_sync(fBl, wl + (nt * 16) * LDX + kt * 16, LDX);
                    wmma::mma_sync(accK[nt], fAh[kt], fBh, accK[nt]);
                    wmma::mma_sync(accK[nt], fAh[kt], fBl, accK[nt]);
                    wmma::mma_sync(accK[nt], fAl[kt], fBh, accK[nt]);
                    wmma::load_matrix_sync(fBh, wh + (32 + nt * 16) * LDX + kt * 16, LDX);
                    wmma::load_matrix_sync(fBl, wl + (32 + nt * 16) * LDX + kt * 16, LDX);
                    wmma::mma_sync(accV[nt], fAh[kt], fBh, accV[nt]);
                    wmma::mma_sync(accV[nt], fAh[kt], fBl, accV[nt]);
                    wmma::mma_sync(accV[nt], fAl[kt], fBh, accV[nt]);
                }
            }
#pragma unroll
            for (int nt = 0; nt < 2; nt++) {
#pragma unroll
                for (int e = 0; e < accK[nt].num_elements; e++)
                    accK[nt].x[e] = __expf(accK[nt].x[e]);
                wmma::store_matrix_sync(ekf + nt * 16 * 132 + wid * 16, accK[nt], 132, wmma::mem_col_major);
                wmma::store_matrix_sync(vvf + nt * 16 * 132 + wid * 16, accV[nt], 132, wmma::mem_col_major);
            }
        }
        __syncthreads();

        // ---- split pass: fp32 -> bf16 hi/lo tiles (in-place overlay) + Z ----
        {
            float er[16], vr[16];
#pragma unroll
            for (int j = 0; j < 4; j++) {
                *(float4*)(er + 4 * j) = *(const float4*)(ekf + sd * 132 + pl + 4 * j);
                *(float4*)(vr + 4 * j) = *(const float4*)(vvf + sd * 132 + pl + 4 * j);
            }
            float zs = 0.f;
#pragma unroll
            for (int j = 0; j < 16; j++) zs += er[j];
            zs += __shfl_xor_sync(0xffffffffu, zs, 1);
            zs += __shfl_xor_sync(0xffffffffu, zs, 2);
            zs += __shfl_xor_sync(0xffffffffu, zs, 4);
            __syncthreads();            // fp32 reads complete before bf16 overlay
#pragma unroll
            for (int j = 0; j < 4; j++) {
                __nv_bfloat16 h0, l0, h1, l1, h2, l2, h3, l3;
                bsplit(er[4 * j], h0, l0); bsplit(er[4 * j + 1], h1, l1);
                bsplit(er[4 * j + 2], h2, l2); bsplit(er[4 * j + 3], h3, l3);
                uint2 ph, plo;
                ph.x  = (u32)__bfloat16_as_ushort(h0) | ((u32)__bfloat16_as_ushort(h1) << 16);
                ph.y  = (u32)__bfloat16_as_ushort(h2) | ((u32)__bfloat16_as_ushort(h3) << 16);
                plo.x = (u32)__bfloat16_as_ushort(l0) | ((u32)__bfloat16_as_ushort(l1) << 16);
                plo.y = (u32)__bfloat16_as_ushort(l2) | ((u32)__bfloat16_as_ushort(l3) << 16);
                *(uint2*)(ekh + sd * LDE + pl + 4 * j) = ph;
                *(uint2*)(ekl + sd * LDE + pl + 4 * j) = plo;
                bsplit(vr[4 * j], h0, l0); bsplit(vr[4 * j + 1], h1, l1);
                bsplit(vr[4 * j + 2], h2, l2); bsplit(vr[4 * j + 3], h3, l3);
                ph.x  = (u32)__bfloat16_as_ushort(h0) | ((u32)__bfloat16_as_ushort(h1) << 16);
                ph.y  = (u32)__bfloat16_as_ushort(h2) | ((u32)__bfloat16_as_ushort(h3) << 16);
                plo.x = (u32)__bfloat16_as_ushort(l0) | ((u32)__bfloat16_as_ushort(l1) << 16);
                plo.y = (u32)__bfloat16_as_ushort(l2) | ((u32)__bfloat16_as_ushort(l3) << 16);
                *(uint2*)(vvh + sd * LDE + pl + 4 * j) = ph;
                *(uint2*)(vvl + sd * LDE + pl + 4 * j) = plo;
            }
            if ((t & 7) == 0)
                atomicAdd(g_Z + (bb * HEADS + h) * DHEAD + sd, zs);
        }
        __syncthreads();

        // ---- ctx GEMM: ctx[d][e] += ek @ vv^T over k=pos, 3-way split ----
        {
            wmma::fragment<wmma::accumulator, 16, 16, 16, float> accC;
            wmma::fill_fragment(accC, 0.f);
#pragma unroll
            for (int kt = 0; kt < 4; kt++) {
                int k0 = kh * 64 + kt * 16;
                wmma::fragment<wmma::matrix_a, 16, 16, 16, __nv_bfloat16, wmma::row_major> cAh, cAl;
                wmma::fragment<wmma::matrix_b, 16, 16, 16, __nv_bfloat16, wmma::col_major> cBh, cBl;
                wmma::load_matrix_sync(cAh, ekh + (mt * 16) * LDE + k0, LDE);
                wmma::load_matrix_sync(cAl, ekl + (mt * 16) * LDE + k0, LDE);
                wmma::load_matrix_sync(cBh, vvh + (ctn * 16) * LDE + k0, LDE);
                wmma::load_matrix_sync(cBl, vvl + (ctn * 16) * LDE + k0, LDE);
                wmma::mma_sync(accC, cAh, cBh, accC);
                wmma::mma_sync(accC, cAh, cBl, accC);
                wmma::mma_sync(accC, cAl, cBh, accC);
            }
            wmma::store_matrix_sync(cb + wid * 320, accC, 20, wmma::mem_row_major);
        }
        __syncthreads();

        // ---- reduce k-halves + atomicAdd ctx ----
#pragma unroll
        for (int j = 0; j < 4; j++) {
            int idx = t + j * 256;       // 0..1023
            int d = idx >> 5, e = idx & 31;
            int bi = (d >> 4) * 2 + (e >> 4);
            float v = cb[bi * 320 + (d & 15) * 20 + (e & 15)]
                    + cb[(4 + bi) * 320 + (d & 15) * 20 + (e & 15)];
            atomicAdd(g_ctx + (size_t)((bb * HEADS + h) * DHEAD + d) * DHEAD + e, v);
        }
        __syncthreads();
    }
}

// ---------------- kernel 2: fold -> split-bf16 M, pre-padded rows [i][LDX] ----------------
__global__ void la_fold_kernel(const float* __restrict__ wout) {
    int bb = blockIdx.x;
    for (int idx = threadIdx.x; idx < HID * CC; idx += blockDim.x) {
        int i = idx >> 6, o = idx & 63;
        int h = i >> 5,   d = i & 31;
        const float* cp = g_ctx + (size_t)((bb * HEADS + h) * DHEAD + d) * DHEAD;
        const float* wp = wout + (size_t)o * HID + h * DHEAD;
        float acc = 0.f;
#pragma unroll
        for (int e = 0; e < 32; e++) acc += wp[e] * cp[e];
        float m = acc / g_Z[(bb * HEADS + h) * DHEAD + d];
        __nv_bfloat16 mh, ml; bsplit(m, mh, ml);
        g_Mh[bb][i * LDX + o] = mh;
        g_Ml[bb][i * LDX + o] = ml;
    }
}

// ===== pass2: LN + per-head (Q GEMM + softmax + y+=q@M) + LN2; q stays on-chip =====
#define P2_XH  0
#define P2_XL  18432
#define P2_WQH 36864      // 32*72*2 = 4608
#define P2_WQL 41472
#define P2_MH  46080      // 4608
#define P2_ML  50688
#define P2_EK  55296      // 32*132*4 = 16896 (also LN scratch)
#define P2_QH  72192      // 128*40*2 = 10240
#define P2_QL  82432
#define P2_PAR 92672      // 5*64 floats
#define P2_BYTES 93952
#define P2_YS  55296      // 64*132*4 = 33792, overlays EK/QH after heads done

__global__ __launch_bounds__(TPB, 2)
void la_pass2_kernel(const float* __restrict__ x, const float* __restrict__ g1,
                     const float* __restrict__ b1,
                     const float* __restrict__ bout, const float* __restrict__ g2,
                     const float* __restrict__ b2, float* __restrict__ out) {
    extern __shared__ char smem[];
    __nv_bfloat16* xh  = (__nv_bfloat16*)(smem + P2_XH);
    __nv_bfloat16* xl  = (__nv_bfloat16*)(smem + P2_XL);
    __nv_bfloat16* wqh = (__nv_bfloat16*)(smem + P2_WQH);
    __nv_bfloat16* wql = (__nv_bfloat16*)(smem + P2_WQL);
    __nv_bfloat16* mh  = (__nv_bfloat16*)(smem + P2_MH);
    __nv_bfloat16* ml  = (__nv_bfloat16*)(smem + P2_ML);
    __nv_bfloat16* qh  = (__nv_bfloat16*)(smem + P2_QH);
    __nv_bfloat16* ql  = (__nv_bfloat16*)(smem + P2_QL);
    float* ekf = (float*)(smem + P2_EK);
    float* ys  = (float*)(smem + P2_YS);
    float* g1s = (float*)(smem + P2_PAR);
    float* b1s = g1s + 64;
    float* g2s = b1s + 64;
    float* b2s = g2s + 64;
    float* bos = b2s + 64;

    const int t   = threadIdx.x;
    const int wid = t >> 5;
    const int bb   = blockIdx.y;
    const int pos0 = blockIdx.x * POSB;

    if (t < 64) {
        g1s[t] = g1[t]; b1s[t] = b1[t];
        g2s[t] = g2[t]; b2s[t] = b2[t]; bos[t] = bout[t];
    }
    ln_to_tiles(x, bb, pos0, t, xh, xl, ekf, g1s, b1s);
    __syncthreads();

    wmma::fragment<wmma::accumulator, 16, 16, 16, float> acc_y[4];
#pragma unroll
    for (int nt = 0; nt < 4; nt++) wmma::fill_fragment(acc_y[nt], 0.f);

    for (int h = 0; h < HEADS; h++) {
        // stage WQ_h + M_h: pure uint4 copies (pre-split, pre-padded)
        {
            uint4* d0 = (uint4*)wqh;
            uint4* d1 = (uint4*)wql;
            uint4* d2 = (uint4*)mh;
            uint4* d3 = (uint4*)ml;
            const uint4* s0 = (const uint4*)g_Wh;
            const uint4* s1 = (const uint4*)g_Wl;
            const uint4* s2 = (const uint4*)g_Mh[bb];
            const uint4* s3 = (const uint4*)g_Ml[bb];
            for (int idx = t; idx < 288; idx += TPB) {
                int src = (h * 32) * 9 + idx;        // rows h*32..h*32+31, 9 uint4/row
                d0[idx] = s0[src];
                d1[idx] = s1[src];
                d2[idx] = s2[src];
                d3[idx] = s3[src];
            }
        }
        __syncthreads();

        // Q GEMM: logits[32 qrows][128 pos]
        {
            wmma::fragment<wmma::accumulator, 16, 16, 16, float> acc[2];
            wmma::fill_fragment(acc[0], 0.f); wmma::fill_fragment(acc[1], 0.f);
#pragma unroll
            for (int kt = 0; kt < 4; kt++) {
                wmma::fragment<wmma::matrix_a, 16, 16, 16, __nv_bfloat16, wmma::row_major> fAh, fAl;
                wmma::load_matrix_sync(fAh, xh + wid * 16 * LDX + kt * 16, LDX);
                wmma::load_matrix_sync(fAl, xl + wid * 16 * LDX + kt * 16, LDX);
#pragma unroll
                for (int nt = 0; nt < 2; nt++) {
                    wmma::fragment<wmma::matrix_b, 16, 16, 16, __nv_bfloat16, wmma::col_major> fBh, fBl;
                    wmma::load_matrix_sync(fBh, wqh + (nt * 16) * LDX + kt * 16, LDX);
                    wmma::load_matrix_sync(fBl, wql + (nt * 16) * LDX + kt * 16, LDX);
                    wmma::mma_sync(acc[nt], fAh, fBh, acc[nt]);
                    wmma::mma_sync(acc[nt], fAh, fBl, acc[nt]);
                    wmma::mma_sync(acc[nt], fAl, fBh, acc[nt]);
                }
            }
            wmma::store_matrix_sync(ekf + wid * 16,            acc[0], 132, wmma::mem_col_major);
            wmma::store_matrix_sync(ekf + 16 * 132 + wid * 16, acc[1], 132, wmma::mem_col_major);
        }
        __syncthreads();

        // softmax per position -> q tiles (ld 40)
        if (t < 128) {
            float qv[32];
            float mx = -1e30f;
#pragma unroll
            for (int d = 0; d < 32; d++) { qv[d] = ekf[d * 132 + t]; mx = fmaxf(mx, qv[d]); }
            float ss = 0.f;
#pragma unroll
            for (int d = 0; d < 32; d++) { qv[d] = __expf(qv[d] - mx); ss += qv[d]; }
            float sc = 0.17677669529663687f / ss;
#pragma unroll
            for (int i = 0; i < 16; i++) {
                __nv_bfloat16 h0, l0, h1, l1;
                bsplit(qv[2 * i] * sc, h0, l0); bsplit(qv[2 * i + 1] * sc, h1, l1);
                *(u32*)(qh + t * LDQ + 2 * i) = (u32)__bfloat16_as_ushort(h0) | ((u32)__bfloat16_as_ushort(h1) << 16);
                *(u32*)(ql + t * LDQ + 2 * i) = (u32)__bfloat16_as_ushort(l0) | ((u32)__bfloat16_as_ushort(l1) << 16);
            }
        }
        __syncthreads();

        // y += q_h @ M_h
#pragma unroll
        for (int kt = 0; kt < 2; kt++) {
            wmma::fragment<wmma::matrix_a, 16, 16, 16, __nv_bfloat16, wmma::row_major> fAh, fAl;
            wmma::load_matrix_sync(fAh, qh + wid * 16 * LDQ + kt * 16, LDQ);
            wmma::load_matrix_sync(fAl, ql + wid * 16 * LDQ + kt * 16, LDQ);
#pragma unroll
            for (int nt = 0; nt < 4; nt++) {
                wmma::fragment<wmma::matrix_b, 16, 16, 16, __nv_bfloat16, wmma::row_major> fBh, fBl;
                wmma::load_matrix_sync(fBh, mh + (kt * 16) * LDX + nt * 16, LDX);
                wmma::load_matrix_sync(fBl, ml + (kt * 16) * LDX + nt * 16, LDX);
                wmma::mma_sync(acc_y[nt], fAh, fBh, acc_y[nt]);
                wmma::mma_sync(acc_y[nt], fAh, fBl, acc_y[nt]);
                wmma::mma_sync(acc_y[nt], fAl, fBh, acc_y[nt]);
            }
        }
        __syncthreads();
    }

#pragma unroll
    for (int nt = 0; nt < 4; nt++)
        wmma::store_matrix_sync(ys + nt * 16 * 132 + wid * 16, acc_y[nt], 132, wmma::mem_col_major);
    __syncthreads();

    if (t < 128) {
        float y[64];
        float s = 0.f, s2 = 0.f;
#pragma unroll
        for (int o = 0; o < 64; o++) {
            float v = ys[o * 132 + t] + bos[o];
            y[o] = v; s += v; s2 += v * v;
        }
        float mn = s * (1.f / 64.f);
        float rs = rsqrtf(s2 * (1.f / 64.f) - mn * mn + 1e-5f);
        float* ob = out + (size_t)bb * CC * NPOS + pos0 + t;
#pragma unroll
        for (int o = 0; o < 64; o++)
            ob[(size_t)o * NPOS] = (y[o] - mn) * rs * g2s[o] + b2s[o];
    }
}

// ---------------- launch ----------------
extern "C" void kernel_launch(void* const* d_in, const int* in_sizes, int n_in,
                              void* d_out, int out_size) {
    (void)in_sizes; (void)n_in; (void)out_size;
    const float* x    = (const float*)d_in[0];
    const float* g1   = (const float*)d_in[1];
    const float* b1   = (const float*)d_in[2];
    const float* wqkv = (const float*)d_in[3];
    const float* wout = (const float*)d_in[4];
    const float* bout = (const float*)d_in[5];
    const float* g2   = (const float*)d_in[6];
    const float* b2   = (const float*)d_in[7];
    float* y = (float*)d_out;

    cudaFuncSetAttribute(la_pass1_kernel, cudaFuncAttributeMaxDynamicSharedMemorySize, P1_BYTES);
    cudaFuncSetAttribute(la_pass2_kernel, cudaFuncAttributeMaxDynamicSharedMemorySize, P2_BYTES);

    la_zero_kernel<<<33, 256>>>(wqkv);
    la_pass1_kernel<<<dim3(NPOS / POSB, BB), TPB, P1_BYTES>>>(x, g1, b1);
    la_fold_kernel<<<BB, 256>>>(wout);
    la_pass2_kernel<<<dim3(NPOS / POSB, BB), TPB, P2_BYTES>>>(x, g1, b1, bout, g2, b2, y);
}